// round 7
// baseline (speedup 1.0000x reference)
#include <cuda_runtime.h>
#include <math.h>

#define N_NODES 100000
#define N_EDGES 1600000
#define NCHUNK 98   // ceil(100000/1024)

// ---------------- scratch (static device globals; vector-typed => aligned) ----------
__device__ int    g_is64;
__device__ int    g_cnt [N_NODES];
__device__ int    g_off [N_NODES];
__device__ float  g_dinv[N_NODES];
__device__ int    g_part[256];
__device__ int    g_src [N_EDGES];
__device__ float4 g_h1[(size_t)N_NODES * 32];   // 100000 x 128 floats
__device__ float4 g_a1[(size_t)N_NODES * 32];
__device__ float2 g_h2[(size_t)N_NODES * 20];   // 100000 x 40 floats

// clamp any graph-derived index into a provably safe range
__device__ __forceinline__ int clampi(int v, int hi) {
    return v < 0 ? 0 : (v >= hi ? hi - 1 : v);
}

// ---------------- dtype probe: int64 edge_index has all odd 32-bit words == 0 -----
__global__ void k_dtype(const unsigned* __restrict__ w) {
    __shared__ unsigned s;
    if (threadIdx.x == 0) s = 0u;
    __syncthreads();
    unsigned acc = 0u;
    for (int i = threadIdx.x; i < 4096; i += 256) acc |= w[2 * i + 1];
    atomicOr(&s, acc);
    __syncthreads();
    if (threadIdx.x == 0) g_is64 = (s == 0u) ? 1 : 0;
}

// edge accessors: w = edge buffer as 32-bit words; always clamped
__device__ __forceinline__ int edge_row(const unsigned* w, int e) {
    int v = g_is64 ? (int)w[2 * (size_t)e] : (int)w[e];
    return clampi(v, N_NODES);
}
__device__ __forceinline__ int edge_col(const unsigned* w, int e) {
    int v = g_is64 ? (int)w[2 * ((size_t)N_EDGES + e)] : (int)w[(size_t)N_EDGES + e];
    return clampi(v, N_NODES);
}

// ---------------- preprocessing: degree + CSR build ----------------
__global__ void k_zero() {
    int i = blockIdx.x * blockDim.x + threadIdx.x;
    if (i < N_NODES) g_cnt[i] = 0;
}

__global__ void k_degree(const unsigned* __restrict__ w) {
    int e = blockIdx.x * blockDim.x + threadIdx.x;
    if (e < N_EDGES) atomicAdd(&g_cnt[edge_col(w, e)], 1);
}

// chunk-local exclusive scan of g_cnt -> g_off, chunk totals -> g_part
__global__ void k_scan1() {
    int tid = threadIdx.x;
    int i = blockIdx.x * 1024 + tid;
    int v = (i < N_NODES) ? g_cnt[i] : 0;
    int lane = tid & 31, wid = tid >> 5;
    int x = v;
    #pragma unroll
    for (int d = 1; d < 32; d <<= 1) {
        int t = __shfl_up_sync(0xffffffffu, x, d);
        if (lane >= d) x += t;
    }
    __shared__ int ws[32];
    if (lane == 31) ws[wid] = x;
    __syncthreads();
    if (wid == 0) {
        int y = ws[lane];
        #pragma unroll
        for (int d = 1; d < 32; d <<= 1) {
            int t = __shfl_up_sync(0xffffffffu, y, d);
            if (lane >= d) y += t;
        }
        ws[lane] = y;
    }
    __syncthreads();
    int incl = x + (wid ? ws[wid - 1] : 0);
    if (i < N_NODES) g_off[i] = incl - v;
    if (tid == 1023) g_part[blockIdx.x] = incl;
}

// exclusive scan of the 98 chunk totals (single block)
__global__ void k_scan2() {
    int tid = threadIdx.x;                       // 128 threads
    int v = (tid < NCHUNK) ? g_part[tid] : 0;
    int lane = tid & 31, wid = tid >> 5;
    int x = v;
    #pragma unroll
    for (int d = 1; d < 32; d <<= 1) {
        int t = __shfl_up_sync(0xffffffffu, x, d);
        if (lane >= d) x += t;
    }
    __shared__ int ws[4];
    if (lane == 31) ws[wid] = x;
    __syncthreads();
    if (tid == 0) {
        int s = 0;
        #pragma unroll
        for (int w = 0; w < 4; w++) { int t = ws[w]; ws[w] = s; s += t; }
    }
    __syncthreads();
    int incl = x + ws[wid];
    if (tid < NCHUNK) g_part[tid] = incl - v;    // exclusive chunk base
}

__global__ void k_scan3() {
    int i = blockIdx.x * blockDim.x + threadIdx.x;
    if (i < N_NODES) {
        g_off[i] += g_part[i >> 10];
        g_dinv[i] = rsqrtf((float)g_cnt[i] + 1.0f);  // +1 for self-loop
    }
}

// fill bumps g_off itself; afterwards g_off[n] = segment END (beg = end - cnt)
__global__ void k_fill(const unsigned* __restrict__ w) {
    int e = blockIdx.x * blockDim.x + threadIdx.x;
    if (e < N_EDGES) {
        int r = edge_row(w, e);
        int c = edge_col(w, e);
        int pos = clampi(atomicAdd(&g_off[c], 1), N_EDGES);
        g_src[pos] = r;
    }
}

// ---------------- GEMM1: h1 = X @ W1  (100000x128 @ 128x128) ----------------
__global__ void k_gemm1(const float* __restrict__ X, const float* __restrict__ W) {
    __shared__ alignas(16) float As[64 * 36];    // 64 rows x 32 k-chunk (pad to 36)
    __shared__ alignas(16) float Ws[32 * 128];   // k-chunk x 128 cols
    int tid = threadIdx.x;
    int rowbase = blockIdx.x * 64;
    int tx = tid & 15, ty = tid >> 4;
    int col0 = tx * 8;

    float acc[4][8];
    #pragma unroll
    for (int i = 0; i < 4; i++)
        #pragma unroll
        for (int j = 0; j < 8; j++) acc[i][j] = 0.f;

    for (int k0 = 0; k0 < 128; k0 += 32) {
        for (int i = tid; i < 512; i += 256) {          // A chunk: 512 float4
            int r = i >> 3, c4 = i & 7;
            int gr = rowbase + r;
            float4 v = (gr < N_NODES) ? ((const float4*)X)[gr * 32 + (k0 >> 2) + c4]
                                      : make_float4(0.f, 0.f, 0.f, 0.f);
            *(float4*)&As[r * 36 + (c4 << 2)] = v;
        }
        for (int i = tid; i < 1024; i += 256) {         // W chunk: 1024 float4
            int r = i >> 5, c4 = i & 31;
            *(float4*)&Ws[r * 128 + (c4 << 2)] = ((const float4*)W)[(size_t)(k0 + r) * 32 + c4];
        }
        __syncthreads();

        #pragma unroll
        for (int kk = 0; kk < 32; kk++) {
            float a[4];
            #pragma unroll
            for (int i = 0; i < 4; i++) a[i] = As[(ty * 4 + i) * 36 + kk];
            float4 w0 = *(const float4*)&Ws[kk * 128 + col0];
            float4 w1 = *(const float4*)&Ws[kk * 128 + col0 + 4];
            float w[8] = {w0.x, w0.y, w0.z, w0.w, w1.x, w1.y, w1.z, w1.w};
            #pragma unroll
            for (int i = 0; i < 4; i++)
                #pragma unroll
                for (int j = 0; j < 8; j++) acc[i][j] += a[i] * w[j];
        }
        __syncthreads();
    }

    #pragma unroll
    for (int i = 0; i < 4; i++) {
        int gr = rowbase + ty * 4 + i;
        if (gr < N_NODES) {
            g_h1[(size_t)gr * 32 + (col0 >> 2)]     = make_float4(acc[i][0], acc[i][1], acc[i][2], acc[i][3]);
            g_h1[(size_t)gr * 32 + (col0 >> 2) + 1] = make_float4(acc[i][4], acc[i][5], acc[i][6], acc[i][7]);
        }
    }
}

// ---------------- aggregation layer 1: warp per node, 128 floats ----------------
__global__ void k_agg1() {
    int n = blockIdx.x * 8 + (threadIdx.x >> 5);
    if (n >= N_NODES) return;
    int l = threadIdx.x & 31;
    float dn = g_dinv[n];
    float4 acc = g_h1[(size_t)n * 32 + l];
    float s0 = dn * dn;                       // self-loop weight
    acc.x *= s0; acc.y *= s0; acc.z *= s0; acc.w *= s0;
    int end = g_off[n], cnt = g_cnt[n], beg = end - cnt;
    for (int j = beg; j < end; j++) {
        int s = clampi(g_src[j], N_NODES);
        float w = g_dinv[s] * dn;
        float4 v = g_h1[(size_t)s * 32 + l];
        acc.x += v.x * w; acc.y += v.y * w; acc.z += v.z * w; acc.w += v.w * w;
    }
    g_a1[(size_t)n * 32 + l] = acc;
}

// ---------------- GEMM2: h2 = relu(a1 + b1) @ W2, K tiled by 32 ----------------
__global__ void k_gemm2(const float* __restrict__ b1, const float* __restrict__ W2) {
    __shared__ alignas(16) float Ws[128 * 40];   // full W2, 20KB
    __shared__ alignas(16) float As[64 * 36];    // 64 x 32 k-chunk
    int tid = threadIdx.x;
    int rowbase = blockIdx.x * 64;

    for (int i = tid; i < 1280; i += 256)
        *(float4*)&Ws[i << 2] = ((const float4*)W2)[i];

    int tx = tid & 7, ty = tid >> 3;   // tx: 5 cols, ty: 2 rows
    int col0 = tx * 5;
    float acc[2][5];
    #pragma unroll
    for (int i = 0; i < 2; i++)
        #pragma unroll
        for (int j = 0; j < 5; j++) acc[i][j] = 0.f;

    for (int k0 = 0; k0 < 128; k0 += 32) {
        for (int i = tid; i < 512; i += 256) {
            int r = i >> 3, c4 = i & 7;
            int gr = rowbase + r;
            float4 v = (gr < N_NODES) ? g_a1[(size_t)gr * 32 + (k0 >> 2) + c4]
                                      : make_float4(0.f, 0.f, 0.f, 0.f);
            float4 b = ((const float4*)b1)[(k0 >> 2) + c4];
            v.x = fmaxf(v.x + b.x, 0.f);
            v.y = fmaxf(v.y + b.y, 0.f);
            v.z = fmaxf(v.z + b.z, 0.f);
            v.w = fmaxf(v.w + b.w, 0.f);
            *(float4*)&As[r * 36 + (c4 << 2)] = v;
        }
        __syncthreads();

        #pragma unroll
        for (int kk = 0; kk < 32; kk++) {
            int k = k0 + kk;
            float a0 = As[(ty * 2 + 0) * 36 + kk];
            float a1 = As[(ty * 2 + 1) * 36 + kk];
            #pragma unroll
            for (int j = 0; j < 5; j++) {
                float w = Ws[k * 40 + col0 + j];
                acc[0][j] += a0 * w;
                acc[1][j] += a1 * w;
            }
        }
        __syncthreads();
    }

    float* H2 = (float*)g_h2;
    #pragma unroll
    for (int i = 0; i < 2; i++) {
        int gr = rowbase + ty * 2 + i;
        if (gr < N_NODES) {
            #pragma unroll
            for (int j = 0; j < 5; j++) H2[(size_t)gr * 40 + col0 + j] = acc[i][j];
        }
    }
}

// ---------------- fused aggregation layer 2 + bias2 + log_softmax ----------------
__global__ void k_agg2_lsm(const float* __restrict__ b2, float* __restrict__ out) {
    int n = blockIdx.x * 8 + (threadIdx.x >> 5);
    if (n >= N_NODES) return;
    int l = threadIdx.x & 31;
    float dn = g_dinv[n];
    float2 acc = make_float2(0.f, 0.f);
    if (l < 20) {
        float2 v = g_h2[(size_t)n * 20 + l];
        acc.x = v.x * dn * dn;
        acc.y = v.y * dn * dn;
    }
    int end = g_off[n], cnt = g_cnt[n], beg = end - cnt;
    for (int j = beg; j < end; j++) {
        int s = clampi(g_src[j], N_NODES);
        float w = g_dinv[s] * dn;
        if (l < 20) {
            float2 v = g_h2[(size_t)s * 20 + l];
            acc.x += v.x * w;
            acc.y += v.y * w;
        }
    }
    if (l < 20) {
        float2 b = ((const float2*)b2)[l];
        acc.x += b.x; acc.y += b.y;
    } else {
        acc.x = -3.4e38f; acc.y = -3.4e38f;
    }
    float m = fmaxf(acc.x, acc.y);
    #pragma unroll
    for (int d = 16; d; d >>= 1) m = fmaxf(m, __shfl_xor_sync(0xffffffffu, m, d));
    float s = (l < 20) ? (expf(acc.x - m) + expf(acc.y - m)) : 0.f;
    #pragma unroll
    for (int d = 16; d; d >>= 1) s += __shfl_xor_sync(0xffffffffu, s, d);
    float lse = m + logf(s);
    if (l < 20) {
        ((float2*)out)[(size_t)n * 20 + l] = make_float2(acc.x - lse, acc.y - lse);
    }
}

// ---------------- launch: bind inputs by SIZE RANK (robust to metadata order) ------
// descending sizes: x (12.8M el / 51.2MB) > edge_index (3.2M el; 25.6MB i64 / 12.8MB i32)
//                   > W1 (16384 / 64KB) > W2 (5120 / 20KB) > b1 (128 / 512B) > b2 (40 / 160B)
// ranking is identical whether in_sizes reports elements or bytes.
extern "C" void kernel_launch(void* const* d_in, const int* in_sizes, int n_in,
                              void* d_out, int out_size) {
    int idx[16];
    for (int i = 0; i < n_in && i < 16; i++) idx[i] = i;
    for (int a = 0; a < n_in - 1; a++)                 // selection sort desc by size
        for (int b = a + 1; b < n_in; b++)
            if (in_sizes[idx[b]] > in_sizes[idx[a]]) { int t = idx[a]; idx[a] = idx[b]; idx[b] = t; }

    const float*    x  = (const float*)   d_in[idx[0]];
    const unsigned* ei = (const unsigned*)d_in[idx[1]];
    const float*    W1 = (const float*)   d_in[idx[2]];
    const float*    W2 = (const float*)   d_in[idx[3]];
    const float*    b1 = (const float*)   d_in[idx[4]];
    const float*    b2 = (const float*)   d_in[idx[5]];
    float* out = (float*)d_out;

    k_dtype <<<1, 256>>>(ei);
    k_zero  <<<(N_NODES + 255) / 256, 256>>>();
    k_degree<<<(N_EDGES + 255) / 256, 256>>>(ei);
    k_scan1 <<<NCHUNK, 1024>>>();
    k_scan2 <<<1, 128>>>();
    k_scan3 <<<(N_NODES + 255) / 256, 256>>>();
    k_fill  <<<(N_EDGES + 255) / 256, 256>>>(ei);

    k_gemm1 <<<(N_NODES + 63) / 64, 256>>>(x, W1);
    k_agg1  <<<(N_NODES + 7) / 8, 256>>>();
    k_gemm2 <<<(N_NODES + 63) / 64, 256>>>(b1, W2);
    k_agg2_lsm<<<(N_NODES + 7) / 8, 256>>>(b2, out);
}

// round 8
// speedup vs baseline: 1.1730x; 1.1730x over previous
#include <cuda_runtime.h>
#include <math.h>

#define N_NODES 100000
#define N_EDGES 1600000
#define NCHUNK 98   // ceil(100000/1024)

// ---------------- scratch (static device globals; vector-typed => aligned) ----------
__device__ int    g_is64;
__device__ int    g_cnt [N_NODES];
__device__ int    g_off [N_NODES];    // chunk-LOCAL exclusive offsets (then local end after fill)
__device__ float  g_dinv[N_NODES];
__device__ int    g_part[256];        // chunk bases after k_scan2
__device__ int    g_src [N_EDGES];
__device__ float4 g_h1[(size_t)N_NODES * 32];   // 100000 x 128 floats
__device__ float4 g_a1[(size_t)N_NODES * 32];
__device__ float2 g_h2[(size_t)N_NODES * 20];   // 100000 x 40 floats

__device__ __forceinline__ int clampi(int v, int hi) {
    return v < 0 ? 0 : (v >= hi ? hi - 1 : v);
}

__device__ __forceinline__ float to_tf32(float x) {
    unsigned u;
    asm("cvt.rna.tf32.f32 %0, %1;" : "=r"(u) : "f"(x));
    return __uint_as_float(u);
}

// ---------------- init: zero degree counters + dtype probe (block 0) ----------------
__global__ void k_init(const unsigned* __restrict__ w) {
    int i = blockIdx.x * 256 + threadIdx.x;
    if (i < N_NODES) g_cnt[i] = 0;
    if (blockIdx.x == 0) {
        __shared__ unsigned s;
        if (threadIdx.x == 0) s = 0u;
        __syncthreads();
        unsigned acc = 0u;
        for (int j = threadIdx.x; j < 4096; j += 256) acc |= w[2 * j + 1];
        atomicOr(&s, acc);
        __syncthreads();
        if (threadIdx.x == 0) g_is64 = (s == 0u) ? 1 : 0;   // int64 => odd words all zero
    }
}

// edge accessors: w = edge buffer as 32-bit words; always clamped
__device__ __forceinline__ int edge_row(const unsigned* w, int e) {
    int v = g_is64 ? (int)w[2 * (size_t)e] : (int)w[e];
    return clampi(v, N_NODES);
}
__device__ __forceinline__ int edge_col(const unsigned* w, int e) {
    int v = g_is64 ? (int)w[2 * ((size_t)N_EDGES + e)] : (int)w[(size_t)N_EDGES + e];
    return clampi(v, N_NODES);
}

__global__ void k_degree(const unsigned* __restrict__ w) {
    int e = blockIdx.x * blockDim.x + threadIdx.x;
    if (e < N_EDGES) atomicAdd(&g_cnt[edge_col(w, e)], 1);
}

// chunk-local exclusive scan of g_cnt -> g_off, chunk totals -> g_part, dinv
__global__ void k_scan1() {
    int tid = threadIdx.x;
    int i = blockIdx.x * 1024 + tid;
    int v = (i < N_NODES) ? g_cnt[i] : 0;
    int lane = tid & 31, wid = tid >> 5;
    int x = v;
    #pragma unroll
    for (int d = 1; d < 32; d <<= 1) {
        int t = __shfl_up_sync(0xffffffffu, x, d);
        if (lane >= d) x += t;
    }
    __shared__ int ws[32];
    if (lane == 31) ws[wid] = x;
    __syncthreads();
    if (wid == 0) {
        int y = ws[lane];
        #pragma unroll
        for (int d = 1; d < 32; d <<= 1) {
            int t = __shfl_up_sync(0xffffffffu, y, d);
            if (lane >= d) y += t;
        }
        ws[lane] = y;
    }
    __syncthreads();
    int incl = x + (wid ? ws[wid - 1] : 0);
    if (i < N_NODES) {
        g_off[i]  = incl - v;                       // chunk-local exclusive
        g_dinv[i] = rsqrtf((float)v + 1.0f);        // +1 self-loop
    }
    if (tid == 1023) g_part[blockIdx.x] = incl;
}

// exclusive scan of the 98 chunk totals -> chunk bases (single block)
__global__ void k_scan2() {
    int tid = threadIdx.x;                       // 128 threads
    int v = (tid < NCHUNK) ? g_part[tid] : 0;
    int lane = tid & 31, wid = tid >> 5;
    int x = v;
    #pragma unroll
    for (int d = 1; d < 32; d <<= 1) {
        int t = __shfl_up_sync(0xffffffffu, x, d);
        if (lane >= d) x += t;
    }
    __shared__ int ws[4];
    if (lane == 31) ws[wid] = x;
    __syncthreads();
    if (tid == 0) {
        int s = 0;
        #pragma unroll
        for (int w = 0; w < 4; w++) { int t = ws[w]; ws[w] = s; s += t; }
    }
    __syncthreads();
    int incl = x + ws[wid];
    if (tid < NCHUNK) g_part[tid] = incl - v;    // exclusive chunk base
}

// fill: global pos = chunk base + bump of chunk-local cursor
__global__ void k_fill(const unsigned* __restrict__ w) {
    int e = blockIdx.x * blockDim.x + threadIdx.x;
    if (e < N_EDGES) {
        int r = edge_row(w, e);
        int c = edge_col(w, e);
        int pos = clampi(g_part[c >> 10] + atomicAdd(&g_off[c], 1), N_EDGES);
        g_src[pos] = r;
    }
}

// node n's CSR segment: end = chunk_base + local_end, beg = end - cnt
__device__ __forceinline__ void seg(int n, int& beg, int& end) {
    end = g_part[n >> 10] + g_off[n];
    beg = end - g_cnt[n];
}

// ---------------- GEMM1: h1 = X @ W1, tf32 tensor cores (mma.m16n8k8) ----------------
// 128x128 tile/block, 8 warps in 4(m) x 2(n); warp tile 32x64 = 2x8 m16n8 atoms.
#define MMA_TF32(cc, aa, bb)                                                      \
    asm volatile("mma.sync.aligned.m16n8k8.row.col.f32.tf32.tf32.f32 "            \
                 "{%0,%1,%2,%3}, {%4,%5,%6,%7}, {%8,%9}, {%0,%1,%2,%3};"          \
                 : "+f"(cc[0]), "+f"(cc[1]), "+f"(cc[2]), "+f"(cc[3])             \
                 : "r"(aa[0]), "r"(aa[1]), "r"(aa[2]), "r"(aa[3]),                \
                   "r"(bb[0]), "r"(bb[1]))

__global__ void k_gemm1(const float* __restrict__ X, const float* __restrict__ W) {
    __shared__ alignas(16) float As [128 * 36];   // 128 rows x 32 k (stride 36) 18KB
    __shared__ alignas(16) float Wst[128 * 36];   // TRANSPOSED: [n][k], stride 36  18KB
    int tid = threadIdx.x;
    int lane = tid & 31, wid = tid >> 5;
    int warp_m = wid & 3, warp_n = wid >> 2;
    int group = lane >> 2, tig = lane & 3;
    int rowbase = blockIdx.x * 128;

    float acc[2][8][4];
    #pragma unroll
    for (int mi = 0; mi < 2; mi++)
        #pragma unroll
        for (int nj = 0; nj < 8; nj++)
            #pragma unroll
            for (int c = 0; c < 4; c++) acc[mi][nj][c] = 0.f;

    for (int k0 = 0; k0 < 128; k0 += 32) {
        // stage A: 128 rows x 8 float4 (tf32-rounded)
        for (int i = tid; i < 1024; i += 256) {
            int r = i >> 3, c4 = i & 7;
            int gr = rowbase + r;
            float4 v = (gr < N_NODES) ? ((const float4*)X)[(size_t)gr * 32 + (k0 >> 2) + c4]
                                      : make_float4(0.f, 0.f, 0.f, 0.f);
            float* dst = &As[r * 36 + (c4 << 2)];
            dst[0] = to_tf32(v.x); dst[1] = to_tf32(v.y);
            dst[2] = to_tf32(v.z); dst[3] = to_tf32(v.w);
        }
        // stage W transposed: read [k][n] float4, write 4 scalars to Wst[n][k]
        for (int i = tid; i < 1024; i += 256) {
            int k = i >> 5, n4 = i & 31;
            float4 v = ((const float4*)W)[(size_t)(k0 + k) * 32 + n4];
            int n = n4 << 2;
            Wst[(n + 0) * 36 + k] = to_tf32(v.x);
            Wst[(n + 1) * 36 + k] = to_tf32(v.y);
            Wst[(n + 2) * 36 + k] = to_tf32(v.z);
            Wst[(n + 3) * 36 + k] = to_tf32(v.w);
        }
        __syncthreads();

        #pragma unroll
        for (int ks = 0; ks < 32; ks += 8) {
            unsigned bf[8][2];
            #pragma unroll
            for (int nj = 0; nj < 8; nj++) {
                int bb = (warp_n * 64 + nj * 8 + group) * 36 + ks + tig;
                bf[nj][0] = __float_as_uint(Wst[bb]);
                bf[nj][1] = __float_as_uint(Wst[bb + 4]);
            }
            unsigned af[2][4];
            #pragma unroll
            for (int mi = 0; mi < 2; mi++) {
                int ra = (warp_m * 32 + mi * 16 + group) * 36 + ks + tig;
                af[mi][0] = __float_as_uint(As[ra]);
                af[mi][1] = __float_as_uint(As[ra + 8 * 36]);
                af[mi][2] = __float_as_uint(As[ra + 4]);
                af[mi][3] = __float_as_uint(As[ra + 8 * 36 + 4]);
            }
            #pragma unroll
            for (int mi = 0; mi < 2; mi++)
                #pragma unroll
                for (int nj = 0; nj < 8; nj++)
                    MMA_TF32(acc[mi][nj], af[mi], bf[nj]);
        }
        __syncthreads();
    }

    float2* H1 = (float2*)g_h1;
    #pragma unroll
    for (int mi = 0; mi < 2; mi++) {
        int row0 = rowbase + warp_m * 32 + mi * 16 + group;
        #pragma unroll
        for (int nj = 0; nj < 8; nj++) {
            int c2 = (warp_n * 64 + nj * 8 + tig * 2) >> 1;
            if (row0 < N_NODES)
                H1[(size_t)row0 * 64 + c2] = make_float2(acc[mi][nj][0], acc[mi][nj][1]);
            if (row0 + 8 < N_NODES)
                H1[(size_t)(row0 + 8) * 64 + c2] = make_float2(acc[mi][nj][2], acc[mi][nj][3]);
        }
    }
}

// ---------------- aggregation layer 1: warp per node, 128 floats ----------------
__global__ void k_agg1() {
    int n = blockIdx.x * 8 + (threadIdx.x >> 5);
    if (n >= N_NODES) return;
    int l = threadIdx.x & 31;
    float dn = g_dinv[n];
    float4 acc = g_h1[(size_t)n * 32 + l];
    float s0 = dn * dn;                       // self-loop weight
    acc.x *= s0; acc.y *= s0; acc.z *= s0; acc.w *= s0;
    int beg, end; seg(n, beg, end);
    for (int j = beg; j < end; j++) {
        int s = clampi(g_src[j], N_NODES);
        float w = g_dinv[s] * dn;
        float4 v = g_h1[(size_t)s * 32 + l];
        acc.x += v.x * w; acc.y += v.y * w; acc.z += v.z * w; acc.w += v.w * w;
    }
    g_a1[(size_t)n * 32 + l] = acc;
}

// ---------------- GEMM2: h2 = relu(a1 + b1) @ W2, fp32 FMA, K tiled by 32 ----------
__global__ void k_gemm2(const float* __restrict__ b1, const float* __restrict__ W2) {
    __shared__ alignas(16) float Ws[128 * 40];   // full W2, 20KB
    __shared__ alignas(16) float As[64 * 36];    // 64 x 32 k-chunk
    int tid = threadIdx.x;
    int rowbase = blockIdx.x * 64;

    for (int i = tid; i < 1280; i += 256)
        *(float4*)&Ws[i << 2] = ((const float4*)W2)[i];

    int tx = tid & 7, ty = tid >> 3;   // tx: 5 cols, ty: 2 rows
    int col0 = tx * 5;
    float acc[2][5];
    #pragma unroll
    for (int i = 0; i < 2; i++)
        #pragma unroll
        for (int j = 0; j < 5; j++) acc[i][j] = 0.f;

    for (int k0 = 0; k0 < 128; k0 += 32) {
        for (int i = tid; i < 512; i += 256) {
            int r = i >> 3, c4 = i & 7;
            int gr = rowbase + r;
            float4 v = (gr < N_NODES) ? g_a1[(size_t)gr * 32 + (k0 >> 2) + c4]
                                      : make_float4(0.f, 0.f, 0.f, 0.f);
            float4 b = ((const float4*)b1)[(k0 >> 2) + c4];
            v.x = fmaxf(v.x + b.x, 0.f);
            v.y = fmaxf(v.y + b.y, 0.f);
            v.z = fmaxf(v.z + b.z, 0.f);
            v.w = fmaxf(v.w + b.w, 0.f);
            *(float4*)&As[r * 36 + (c4 << 2)] = v;
        }
        __syncthreads();

        #pragma unroll
        for (int kk = 0; kk < 32; kk++) {
            int k = k0 + kk;
            float a0 = As[(ty * 2 + 0) * 36 + kk];
            float a1 = As[(ty * 2 + 1) * 36 + kk];
            #pragma unroll
            for (int j = 0; j < 5; j++) {
                float w = Ws[k * 40 + col0 + j];
                acc[0][j] += a0 * w;
                acc[1][j] += a1 * w;
            }
        }
        __syncthreads();
    }

    float* H2 = (float*)g_h2;
    #pragma unroll
    for (int i = 0; i < 2; i++) {
        int gr = rowbase + ty * 2 + i;
        if (gr < N_NODES) {
            #pragma unroll
            for (int j = 0; j < 5; j++) H2[(size_t)gr * 40 + col0 + j] = acc[i][j];
        }
    }
}

// ---------------- fused aggregation layer 2 + bias2 + log_softmax ----------------
__global__ void k_agg2_lsm(const float* __restrict__ b2, float* __restrict__ out) {
    int n = blockIdx.x * 8 + (threadIdx.x >> 5);
    if (n >= N_NODES) return;
    int l = threadIdx.x & 31;
    float dn = g_dinv[n];
    float2 acc = make_float2(0.f, 0.f);
    if (l < 20) {
        float2 v = g_h2[(size_t)n * 20 + l];
        acc.x = v.x * dn * dn;
        acc.y = v.y * dn * dn;
    }
    int beg, end; seg(n, beg, end);
    for (int j = beg; j < end; j++) {
        int s = clampi(g_src[j], N_NODES);
        float w = g_dinv[s] * dn;
        if (l < 20) {
            float2 v = g_h2[(size_t)s * 20 + l];
            acc.x += v.x * w;
            acc.y += v.y * w;
        }
    }
    if (l < 20) {
        float2 b = ((const float2*)b2)[l];
        acc.x += b.x; acc.y += b.y;
    } else {
        acc.x = -3.4e38f; acc.y = -3.4e38f;
    }
    float m = fmaxf(acc.x, acc.y);
    #pragma unroll
    for (int d = 16; d; d >>= 1) m = fmaxf(m, __shfl_xor_sync(0xffffffffu, m, d));
    float s = (l < 20) ? (expf(acc.x - m) + expf(acc.y - m)) : 0.f;
    #pragma unroll
    for (int d = 16; d; d >>= 1) s += __shfl_xor_sync(0xffffffffu, s, d);
    float lse = m + logf(s);
    if (l < 20) {
        ((float2*)out)[(size_t)n * 20 + l] = make_float2(acc.x - lse, acc.y - lse);
    }
}

// ---------------- launch: bind inputs by SIZE RANK (robust, validated R7) ----------
extern "C" void kernel_launch(void* const* d_in, const int* in_sizes, int n_in,
                              void* d_out, int out_size) {
    int idx[16];
    for (int i = 0; i < n_in && i < 16; i++) idx[i] = i;
    for (int a = 0; a < n_in - 1; a++)
        for (int b = a + 1; b < n_in; b++)
            if (in_sizes[idx[b]] > in_sizes[idx[a]]) { int t = idx[a]; idx[a] = idx[b]; idx[b] = t; }

    const float*    x  = (const float*)   d_in[idx[0]];
    const unsigned* ei = (const unsigned*)d_in[idx[1]];
    const float*    W1 = (const float*)   d_in[idx[2]];
    const float*    W2 = (const float*)   d_in[idx[3]];
    const float*    b1 = (const float*)   d_in[idx[4]];
    const float*    b2 = (const float*)   d_in[idx[5]];
    float* out = (float*)d_out;

    k_init  <<<(N_NODES + 255) / 256, 256>>>(ei);     // launch 0
    k_degree<<<(N_EDGES + 255) / 256, 256>>>(ei);     // launch 1
    k_scan1 <<<NCHUNK, 1024>>>();                     // launch 2
    k_scan2 <<<1, 128>>>();                           // launch 3
    k_fill  <<<(N_EDGES + 255) / 256, 256>>>(ei);     // launch 4
    k_gemm1 <<<(N_NODES + 127) / 128, 256>>>(x, W1);  // launch 5  <- ncu -s 5 captures this
    k_agg1  <<<(N_NODES + 7) / 8, 256>>>();           // launch 6
    k_gemm2 <<<(N_NODES + 63) / 64, 256>>>(b1, W2);   // launch 7
    k_agg2_lsm<<<(N_NODES + 7) / 8, 256>>>(b2, out);  // launch 8
}

// round 9
// speedup vs baseline: 1.2022x; 1.0249x over previous
#include <cuda_runtime.h>
#include <cuda_bf16.h>
#include <math.h>

#define N_NODES 100000
#define N_EDGES 1600000
#define NCHUNK 98   // ceil(100000/1024)

// ---------------- scratch (static device globals; vector-typed => aligned) ----------
__device__ int    g_is64;
__device__ int    g_cnt [N_NODES];
__device__ int    g_off [N_NODES];    // chunk-LOCAL exclusive offsets (then local end after fill)
__device__ float  g_dinv[N_NODES];
__device__ int    g_part[256];        // chunk bases after k_scan2
__device__ int    g_src [N_EDGES];
__device__ __nv_bfloat162 g_h1b[(size_t)N_NODES * 64];  // 100000 x 128 in bf16 (256B/row)
__device__ float4 g_a1[(size_t)N_NODES * 32];
__device__ float2 g_h2[(size_t)N_NODES * 20];   // 100000 x 40 floats

__device__ __forceinline__ int clampi(int v, int hi) {
    return v < 0 ? 0 : (v >= hi ? hi - 1 : v);
}

__device__ __forceinline__ float to_tf32(float x) {
    unsigned u;
    asm("cvt.rna.tf32.f32 %0, %1;" : "=r"(u) : "f"(x));
    return __uint_as_float(u);
}

// ---------------- init: zero degree counters + dtype probe (block 0) ----------------
__global__ void k_init(const unsigned* __restrict__ w) {
    int i = blockIdx.x * 256 + threadIdx.x;
    if (i < N_NODES) g_cnt[i] = 0;
    if (blockIdx.x == 0) {
        __shared__ unsigned s;
        if (threadIdx.x == 0) s = 0u;
        __syncthreads();
        unsigned acc = 0u;
        for (int j = threadIdx.x; j < 4096; j += 256) acc |= w[2 * j + 1];
        atomicOr(&s, acc);
        __syncthreads();
        if (threadIdx.x == 0) g_is64 = (s == 0u) ? 1 : 0;   // int64 => odd words all zero
    }
}

// edge accessors: w = edge buffer as 32-bit words; always clamped
__device__ __forceinline__ int edge_row(const unsigned* w, int e) {
    int v = g_is64 ? (int)w[2 * (size_t)e] : (int)w[e];
    return clampi(v, N_NODES);
}
__device__ __forceinline__ int edge_col(const unsigned* w, int e) {
    int v = g_is64 ? (int)w[2 * ((size_t)N_EDGES + e)] : (int)w[(size_t)N_EDGES + e];
    return clampi(v, N_NODES);
}

__global__ void k_degree(const unsigned* __restrict__ w) {
    int e = blockIdx.x * blockDim.x + threadIdx.x;
    if (e < N_EDGES) atomicAdd(&g_cnt[edge_col(w, e)], 1);
}

// chunk-local exclusive scan of g_cnt -> g_off, chunk totals -> g_part, dinv
__global__ void k_scan1() {
    int tid = threadIdx.x;
    int i = blockIdx.x * 1024 + tid;
    int v = (i < N_NODES) ? g_cnt[i] : 0;
    int lane = tid & 31, wid = tid >> 5;
    int x = v;
    #pragma unroll
    for (int d = 1; d < 32; d <<= 1) {
        int t = __shfl_up_sync(0xffffffffu, x, d);
        if (lane >= d) x += t;
    }
    __shared__ int ws[32];
    if (lane == 31) ws[wid] = x;
    __syncthreads();
    if (wid == 0) {
        int y = ws[lane];
        #pragma unroll
        for (int d = 1; d < 32; d <<= 1) {
            int t = __shfl_up_sync(0xffffffffu, y, d);
            if (lane >= d) y += t;
        }
        ws[lane] = y;
    }
    __syncthreads();
    int incl = x + (wid ? ws[wid - 1] : 0);
    if (i < N_NODES) {
        g_off[i]  = incl - v;                       // chunk-local exclusive
        g_dinv[i] = rsqrtf((float)v + 1.0f);        // +1 self-loop
    }
    if (tid == 1023) g_part[blockIdx.x] = incl;
}

// exclusive scan of the 98 chunk totals -> chunk bases (single block)
__global__ void k_scan2() {
    int tid = threadIdx.x;                       // 128 threads
    int v = (tid < NCHUNK) ? g_part[tid] : 0;
    int lane = tid & 31, wid = tid >> 5;
    int x = v;
    #pragma unroll
    for (int d = 1; d < 32; d <<= 1) {
        int t = __shfl_up_sync(0xffffffffu, x, d);
        if (lane >= d) x += t;
    }
    __shared__ int ws[4];
    if (lane == 31) ws[wid] = x;
    __syncthreads();
    if (tid == 0) {
        int s = 0;
        #pragma unroll
        for (int w = 0; w < 4; w++) { int t = ws[w]; ws[w] = s; s += t; }
    }
    __syncthreads();
    int incl = x + ws[wid];
    if (tid < NCHUNK) g_part[tid] = incl - v;    // exclusive chunk base
}

// fill: global pos = chunk base + bump of chunk-local cursor
__global__ void k_fill(const unsigned* __restrict__ w) {
    int e = blockIdx.x * blockDim.x + threadIdx.x;
    if (e < N_EDGES) {
        int r = edge_row(w, e);
        int c = edge_col(w, e);
        int pos = clampi(g_part[c >> 10] + atomicAdd(&g_off[c], 1), N_EDGES);
        g_src[pos] = r;
    }
}

// node n's CSR segment: end = chunk_base + local_end, beg = end - cnt
__device__ __forceinline__ void seg(int n, int& beg, int& end) {
    end = g_part[n >> 10] + g_off[n];
    beg = end - g_cnt[n];
}

// ---------------- GEMM1: h1 = X @ W1, tf32 tensor cores, bf16 output ---------------
#define MMA_TF32(cc, aa, bb)                                                      \
    asm volatile("mma.sync.aligned.m16n8k8.row.col.f32.tf32.tf32.f32 "            \
                 "{%0,%1,%2,%3}, {%4,%5,%6,%7}, {%8,%9}, {%0,%1,%2,%3};"          \
                 : "+f"(cc[0]), "+f"(cc[1]), "+f"(cc[2]), "+f"(cc[3])             \
                 : "r"(aa[0]), "r"(aa[1]), "r"(aa[2]), "r"(aa[3]),                \
                   "r"(bb[0]), "r"(bb[1]))

__global__ void k_gemm1(const float* __restrict__ X, const float* __restrict__ W) {
    __shared__ alignas(16) float As [128 * 36];   // 128 rows x 32 k (stride 36) 18KB
    __shared__ alignas(16) float Wst[128 * 36];   // TRANSPOSED: [n][k], stride 36  18KB
    int tid = threadIdx.x;
    int lane = tid & 31, wid = tid >> 5;
    int warp_m = wid & 3, warp_n = wid >> 2;
    int group = lane >> 2, tig = lane & 3;
    int rowbase = blockIdx.x * 128;

    float acc[2][8][4];
    #pragma unroll
    for (int mi = 0; mi < 2; mi++)
        #pragma unroll
        for (int nj = 0; nj < 8; nj++)
            #pragma unroll
            for (int c = 0; c < 4; c++) acc[mi][nj][c] = 0.f;

    for (int k0 = 0; k0 < 128; k0 += 32) {
        for (int i = tid; i < 1024; i += 256) {         // stage A (tf32-rounded)
            int r = i >> 3, c4 = i & 7;
            int gr = rowbase + r;
            float4 v = (gr < N_NODES) ? ((const float4*)X)[(size_t)gr * 32 + (k0 >> 2) + c4]
                                      : make_float4(0.f, 0.f, 0.f, 0.f);
            float* dst = &As[r * 36 + (c4 << 2)];
            dst[0] = to_tf32(v.x); dst[1] = to_tf32(v.y);
            dst[2] = to_tf32(v.z); dst[3] = to_tf32(v.w);
        }
        for (int i = tid; i < 1024; i += 256) {         // stage W transposed
            int k = i >> 5, n4 = i & 31;
            float4 v = ((const float4*)W)[(size_t)(k0 + k) * 32 + n4];
            int n = n4 << 2;
            Wst[(n + 0) * 36 + k] = to_tf32(v.x);
            Wst[(n + 1) * 36 + k] = to_tf32(v.y);
            Wst[(n + 2) * 36 + k] = to_tf32(v.z);
            Wst[(n + 3) * 36 + k] = to_tf32(v.w);
        }
        __syncthreads();

        #pragma unroll
        for (int ks = 0; ks < 32; ks += 8) {
            unsigned bf[8][2];
            #pragma unroll
            for (int nj = 0; nj < 8; nj++) {
                int bb = (warp_n * 64 + nj * 8 + group) * 36 + ks + tig;
                bf[nj][0] = __float_as_uint(Wst[bb]);
                bf[nj][1] = __float_as_uint(Wst[bb + 4]);
            }
            unsigned af[2][4];
            #pragma unroll
            for (int mi = 0; mi < 2; mi++) {
                int ra = (warp_m * 32 + mi * 16 + group) * 36 + ks + tig;
                af[mi][0] = __float_as_uint(As[ra]);
                af[mi][1] = __float_as_uint(As[ra + 8 * 36]);
                af[mi][2] = __float_as_uint(As[ra + 4]);
                af[mi][3] = __float_as_uint(As[ra + 8 * 36 + 4]);
            }
            #pragma unroll
            for (int mi = 0; mi < 2; mi++)
                #pragma unroll
                for (int nj = 0; nj < 8; nj++)
                    MMA_TF32(acc[mi][nj], af[mi], bf[nj]);
        }
        __syncthreads();
    }

    // epilogue: pack fp32 accumulators to bf16x2
    #pragma unroll
    for (int mi = 0; mi < 2; mi++) {
        int row0 = rowbase + warp_m * 32 + mi * 16 + group;
        #pragma unroll
        for (int nj = 0; nj < 8; nj++) {
            int c2 = (warp_n * 64 + nj * 8 + tig * 2) >> 1;   // bf162 column index
            if (row0 < N_NODES)
                g_h1b[(size_t)row0 * 64 + c2] =
                    __floats2bfloat162_rn(acc[mi][nj][0], acc[mi][nj][1]);
            if (row0 + 8 < N_NODES)
                g_h1b[(size_t)(row0 + 8) * 64 + c2] =
                    __floats2bfloat162_rn(acc[mi][nj][2], acc[mi][nj][3]);
        }
    }
}

// ---------------- aggregation layer 1: warp per node, bf16 gather (8B/lane) --------
__global__ void k_agg1() {
    int n = blockIdx.x * 8 + (threadIdx.x >> 5);
    if (n >= N_NODES) return;
    int l = threadIdx.x & 31;
    float dn = g_dinv[n];
    const uint2* H = (const uint2*)g_h1b;      // one uint2 = 2 x bf162 = 4 cols
    float4 acc;
    {
        uint2 p = H[(size_t)n * 32 + l];
        float2 lo = __bfloat1622float2(*(__nv_bfloat162*)&p.x);
        float2 hi = __bfloat1622float2(*(__nv_bfloat162*)&p.y);
        float s0 = dn * dn;                    // self-loop weight
        acc = make_float4(lo.x * s0, lo.y * s0, hi.x * s0, hi.y * s0);
    }
    int beg, end; seg(n, beg, end);
    for (int j = beg; j < end; j++) {
        int s = clampi(g_src[j], N_NODES);
        float w = g_dinv[s] * dn;
        uint2 p = H[(size_t)s * 32 + l];
        float2 lo = __bfloat1622float2(*(__nv_bfloat162*)&p.x);
        float2 hi = __bfloat1622float2(*(__nv_bfloat162*)&p.y);
        acc.x += lo.x * w; acc.y += lo.y * w;
        acc.z += hi.x * w; acc.w += hi.y * w;
    }
    g_a1[(size_t)n * 32 + l] = acc;
}

// ---------------- GEMM2: h2 = relu(a1 + b1) @ W2, fp32 FMA, K tiled by 32 ----------
__global__ void k_gemm2(const float* __restrict__ b1, const float* __restrict__ W2) {
    __shared__ alignas(16) float Ws[128 * 40];   // full W2, 20KB
    __shared__ alignas(16) float As[64 * 36];    // 64 x 32 k-chunk
    int tid = threadIdx.x;
    int rowbase = blockIdx.x * 64;

    for (int i = tid; i < 1280; i += 256)
        *(float4*)&Ws[i << 2] = ((const float4*)W2)[i];

    int tx = tid & 7, ty = tid >> 3;   // tx: 5 cols, ty: 2 rows
    int col0 = tx * 5;
    float acc[2][5];
    #pragma unroll
    for (int i = 0; i < 2; i++)
        #pragma unroll
        for (int j = 0; j < 5; j++) acc[i][j] = 0.f;

    for (int k0 = 0; k0 < 128; k0 += 32) {
        for (int i = tid; i < 512; i += 256) {
            int r = i >> 3, c4 = i & 7;
            int gr = rowbase + r;
            float4 v = (gr < N_NODES) ? g_a1[(size_t)gr * 32 + (k0 >> 2) + c4]
                                      : make_float4(0.f, 0.f, 0.f, 0.f);
            float4 b = ((const float4*)b1)[(k0 >> 2) + c4];
            v.x = fmaxf(v.x + b.x, 0.f);
            v.y = fmaxf(v.y + b.y, 0.f);
            v.z = fmaxf(v.z + b.z, 0.f);
            v.w = fmaxf(v.w + b.w, 0.f);
            *(float4*)&As[r * 36 + (c4 << 2)] = v;
        }
        __syncthreads();

        #pragma unroll
        for (int kk = 0; kk < 32; kk++) {
            int k = k0 + kk;
            float a0 = As[(ty * 2 + 0) * 36 + kk];
            float a1 = As[(ty * 2 + 1) * 36 + kk];
            #pragma unroll
            for (int j = 0; j < 5; j++) {
                float w = Ws[k * 40 + col0 + j];
                acc[0][j] += a0 * w;
                acc[1][j] += a1 * w;
            }
        }
        __syncthreads();
    }

    float* H2 = (float*)g_h2;
    #pragma unroll
    for (int i = 0; i < 2; i++) {
        int gr = rowbase + ty * 2 + i;
        if (gr < N_NODES) {
            #pragma unroll
            for (int j = 0; j < 5; j++) H2[(size_t)gr * 40 + col0 + j] = acc[i][j];
        }
    }
}

// ---------------- fused aggregation layer 2 + bias2 + log_softmax ----------------
__global__ void k_agg2_lsm(const float* __restrict__ b2, float* __restrict__ out) {
    int n = blockIdx.x * 8 + (threadIdx.x >> 5);
    if (n >= N_NODES) return;
    int l = threadIdx.x & 31;
    float dn = g_dinv[n];
    float2 acc = make_float2(0.f, 0.f);
    if (l < 20) {
        float2 v = g_h2[(size_t)n * 20 + l];
        acc.x = v.x * dn * dn;
        acc.y = v.y * dn * dn;
    }
    int beg, end; seg(n, beg, end);
    for (int j = beg; j < end; j++) {
        int s = clampi(g_src[j], N_NODES);
        float w = g_dinv[s] * dn;
        if (l < 20) {
            float2 v = g_h2[(size_t)s * 20 + l];
            acc.x += v.x * w;
            acc.y += v.y * w;
        }
    }
    if (l < 20) {
        float2 b = ((const float2*)b2)[l];
        acc.x += b.x; acc.y += b.y;
    } else {
        acc.x = -3.4e38f; acc.y = -3.4e38f;
    }
    float m = fmaxf(acc.x, acc.y);
    #pragma unroll
    for (int d = 16; d; d >>= 1) m = fmaxf(m, __shfl_xor_sync(0xffffffffu, m, d));
    float s = (l < 20) ? (expf(acc.x - m) + expf(acc.y - m)) : 0.f;
    #pragma unroll
    for (int d = 16; d; d >>= 1) s += __shfl_xor_sync(0xffffffffu, s, d);
    float lse = m + logf(s);
    if (l < 20) {
        ((float2*)out)[(size_t)n * 20 + l] = make_float2(acc.x - lse, acc.y - lse);
    }
}

// ---------------- launch: bind inputs by SIZE RANK (robust, validated R7) ----------
extern "C" void kernel_launch(void* const* d_in, const int* in_sizes, int n_in,
                              void* d_out, int out_size) {
    int idx[16];
    for (int i = 0; i < n_in && i < 16; i++) idx[i] = i;
    for (int a = 0; a < n_in - 1; a++)
        for (int b = a + 1; b < n_in; b++)
            if (in_sizes[idx[b]] > in_sizes[idx[a]]) { int t = idx[a]; idx[a] = idx[b]; idx[b] = t; }

    const float*    x  = (const float*)   d_in[idx[0]];
    const unsigned* ei = (const unsigned*)d_in[idx[1]];
    const float*    W1 = (const float*)   d_in[idx[2]];
    const float*    W2 = (const float*)   d_in[idx[3]];
    const float*    b1 = (const float*)   d_in[idx[4]];
    const float*    b2 = (const float*)   d_in[idx[5]];
    float* out = (float*)d_out;

    k_init  <<<(N_NODES + 255) / 256, 256>>>(ei);
    k_degree<<<(N_EDGES + 255) / 256, 256>>>(ei);
    k_scan1 <<<NCHUNK, 1024>>>();
    k_scan2 <<<1, 128>>>();
    k_fill  <<<(N_EDGES + 255) / 256, 256>>>(ei);
    k_gemm1 <<<(N_NODES + 127) / 128, 256>>>(x, W1);
    k_agg1  <<<(N_NODES + 7) / 8, 256>>>();
    k_gemm2 <<<(N_NODES + 63) / 64, 256>>>(b1, W2);
    k_agg2_lsm<<<(N_NODES + 7) / 8, 256>>>(b2, out);
}